// round 17
// baseline (speedup 1.0000x reference)
#include <cuda_runtime.h>
#include <cuda_bf16.h>
#include <cstdint>

// Problem constants
#define B_    32
#define C_    64
#define HW_   1024
#define N_    32768         // B*H*W
#define K_    1024
#define TMV   64            // points per tile
#define NTC   128           // codes per task (slice)
#define NTASK 4096          // 512 tiles x 8 slices, task = tile*8 + slice
#define NBLK  296           // persistent blocks (2 per SM, all co-resident)
#define TPB   14            // tasks per block (contiguous run)

// ---------------------------------------------------------------------------
// Scratch (no cudaMalloc allowed)
// ---------------------------------------------------------------------------
__device__ __align__(16) unsigned short g_c1[K_ * C_];  // bf16 codebook [k][c]
__device__ float g_hn[K_];                    // 0.5*||c_k||^2
__device__ unsigned long long g_best[N_];     // packed (monotone dist | idx)
__device__ unsigned int g_cnt = 0;            // barrier count (self-resetting)
__device__ volatile unsigned int g_sense = 0; // barrier sense (monotone)

// Monotone float<->uint order-preserving mapping
__device__ __forceinline__ unsigned int fkey(float f) {
    unsigned int u = __float_as_uint(f);
    return (u & 0x80000000u) ? ~u : (u | 0x80000000u);
}
__device__ __forceinline__ float fkey_dec(unsigned int k) {
    return (k & 0x80000000u) ? __uint_as_float(k & 0x7fffffffu)
                             : __uint_as_float(~k);
}

__device__ __forceinline__ unsigned int smem_u32(const void* p) {
    unsigned int a;
    asm("{ .reg .u64 t; cvta.to.shared.u64 t, %1; cvt.u32.u64 %0, t; }"
        : "=r"(a) : "l"(p));
    return a;
}

__device__ __forceinline__ void cp_async16(unsigned int dst, const void* src) {
    asm volatile("cp.async.cg.shared.global [%0], [%1], 16;"
                 :: "r"(dst), "l"(src) : "memory");
}
#define CP_COMMIT() asm volatile("cp.async.commit_group;" ::: "memory")

// Sense-reversing grid barrier. All NBLK blocks are co-resident (grid ==
// residency at occ 2), so spinning is safe. count self-resets each pass;
// sense only increments (replay-safe). '!=' exit is robust to later bumps.
__device__ __forceinline__ void grid_barrier(int tid) {
    __threadfence();
    __syncthreads();
    if (tid == 0) {
        unsigned int s0 = g_sense;
        unsigned int old = atomicAdd(&g_cnt, 1);
        if (old == NBLK - 1) {
            g_cnt = 0;
            __threadfence();
            g_sense = s0 + 1;
        } else {
            while (g_sense == s0) __nanosleep(40);
        }
        __threadfence();
    }
    __syncthreads();
}

// ---------------------------------------------------------------------------
// smem layout (dynamic, 63008 B/CTA -> occ 2)
// ---------------------------------------------------------------------------
#define XF_OFF   0                     // fp32 x [64 c][64 m] : 16384
#define XB_OFF   16384                 // bf16 x [64 m][128B] swizzled : 8192
#define CB0_OFF  24576                 // 2 bufs x (cb 16384 + hn 512)
#define CBUF_SZ  16896
#define SS_OFF   (CB0_OFF + 2 * CBUF_SZ)   // 58368 : 256
#define SRM_OFF  (SS_OFF + 256)            // 58624 : 256
#define QC_OFF   (SRM_OFF + 256)           // 58880 : 16
#define OVF_OFF  (QC_OFF + 16)             // 58896 : 16
#define QU_OFF   (OVF_OFF + 16)            // 58912
#define QCAP     1024
#define SMEM_SZ  (QU_OFF + QCAP * 4)       // 63008

__device__ __forceinline__ void stage_x(unsigned int sb, const float* __restrict__ z,
                                        int tile, int tid) {
    const int n0  = tile * TMV;
    const int b   = n0 >> 10;
    const int hw0 = n0 & 1023;
    const char* zsrc = (const char*)(z + (size_t)b * C_ * HW_ + hw0);
#pragma unroll
    for (int i = 0; i < 4; ++i) {
        int idx = tid + i * 256;           // 0..1023 16B chunks
        int c   = idx >> 4;
        int o   = (idx & 15) * 16;
        cp_async16(sb + XF_OFF + idx * 16, zsrc + (size_t)c * HW_ * 4 + o);
    }
}

__device__ __forceinline__ void stage_c(unsigned int cbbase, int task, int tid) {
    const int s = task & 7;
    const char* csrc = (const char*)(g_c1 + (size_t)s * NTC * C_);
    const char* hsrc = (const char*)(g_hn + s * NTC);
#pragma unroll
    for (int i = 0; i < 4; ++i) {
        int idx = tid + i * 256;           // 0..1023 chunks
        int row = idx >> 3;
        int chk = idx & 7;
        cp_async16(cbbase + row * 128 + ((chk ^ (row & 7)) * 16),
                   csrc + idx * 16);
    }
    if (tid < 32) cp_async16(cbbase + 16384 + tid * 16, hsrc + tid * 16);
}

// ---------------------------------------------------------------------------
// ONE persistent kernel: prep -> barrier -> tasks -> barrier -> finalize.
// ---------------------------------------------------------------------------
__global__ __launch_bounds__(256, 2)
void vq_kernel(const float* __restrict__ z, const float* __restrict__ cb,
               float* __restrict__ out) {
    extern __shared__ char smem[];
    const unsigned int sb0 = smem_u32(smem);
    float*        xf  = (float*)(smem + XF_OFF);
    float*        sS  = (float*)(smem + SS_OFF);
    unsigned int* srm = (unsigned int*)(smem + SRM_OFF);
    int*          qc  = (int*)(smem + QC_OFF);
    unsigned int* ovf = (unsigned int*)(smem + OVF_OFF);
    int*          qu  = (int*)(smem + QU_OFF);

    const int tid  = threadIdx.x;
    const int wid  = tid >> 5;
    const int lane = tid & 31;
    const int bid  = blockIdx.x;

    // ==== Phase 0: prep (codebook bf16 + norms; g_best init) ====
    if (bid < 256 && tid < 32) {
        const int k   = bid * 4 + (tid >> 3);        // 4 rows per block
        const int sub = tid & 7;                     // 8 threads per row
        const size_t base = (size_t)k * C_ + sub * 8;
        float4 va = *(const float4*)&cb[base];
        float4 vb = *(const float4*)&cb[base + 4];
        float xv[8] = {va.x, va.y, va.z, va.w, vb.x, vb.y, vb.z, vb.w};
        float s = 0.f;
        uint4 p;
        unsigned short* sp = (unsigned short*)&p;
#pragma unroll
        for (int j = 0; j < 8; ++j) {
            float x = xv[j];
            s += x * x;
            sp[j] = __bfloat16_as_ushort(__float2bfloat16(x));
        }
        *(uint4*)&g_c1[base] = p;
        s += __shfl_xor_sync(0xffffffffu, s, 1, 8);
        s += __shfl_xor_sync(0xffffffffu, s, 2, 8);
        s += __shfl_xor_sync(0xffffffffu, s, 4, 8);
        if (sub == 0) g_hn[k] = 0.5f * s;
    }
    for (int i = bid * 256 + tid; i < N_; i += NBLK * 256)
        g_best[i] = 0xFFFFFFFFFFFFFFFFull;

    grid_barrier(tid);

    // ==== Phase 1: task loop (contiguous slice runs per tile) ====
    const int start = bid * TPB;
    const int end   = (start + TPB < NTASK) ? start + TPB : NTASK;

    int t   = start;
    int cur = 0;
    bool needA = true;
    if (t < end) {
        stage_x(sb0, z, t >> 3, tid);
        stage_c(sb0 + CB0_OFF, t, tid);
        CP_COMMIT();
    }

    while (t < end) {
        const int  tn   = t + 1;
        const bool same = (tn < end) && ((tn >> 3) == (t >> 3));
        if (same) {
            stage_c(sb0 + CB0_OFF + (cur ^ 1) * CBUF_SZ, tn, tid);
            CP_COMMIT();
        }
        if (same)
            asm volatile("cp.async.wait_group 1;" ::: "memory");
        else
            asm volatile("cp.async.wait_group 0;" ::: "memory");

        // ---- Phase A (once per tile): fp32 [c][m] -> bf16 [m][c] + sum|x| ----
        if (needA) {
            __syncthreads();               // make staged xf visible to all
            const int m  = tid >> 2;
            const int c0 = (tid & 3) * 16;
            float v[16];
            float S = 0.f;
#pragma unroll
            for (int j = 0; j < 16; ++j) {
                v[j] = xf[(c0 + j) * 64 + m];
                S += fabsf(v[j]);
            }
            unsigned int pk[8];
#pragma unroll
            for (int j = 0; j < 8; ++j)
                asm("cvt.rn.bf16x2.f32 %0, %1, %2;"
                    : "=r"(pk[j]) : "f"(v[j * 2 + 1]), "f"(v[j * 2]));
            const int cb0i = 2 * (tid & 3);
#pragma unroll
            for (int g = 0; g < 2; ++g) {
                unsigned int addr = sb0 + XB_OFF + m * 128
                                  + (((cb0i + g) ^ (m & 7)) * 16);
                asm volatile("st.shared.v4.b32 [%0], {%1,%2,%3,%4};"
                             :: "r"(addr), "r"(pk[g*4+0]), "r"(pk[g*4+1]),
                                "r"(pk[g*4+2]), "r"(pk[g*4+3]) : "memory");
            }
            S += __shfl_xor_sync(0xffffffffu, S, 1, 4);
            S += __shfl_xor_sync(0xffffffffu, S, 2, 4);
            if ((tid & 3) == 0) sS[m] = S;
            needA = false;
        }
        if (tid < 64) srm[tid] = 0xFFFFFFFFu;
        if (tid == 0) *qc = 0;
        if (tid < 2)  ovf[tid] = 0u;
        __syncthreads();

        const unsigned int cbbase = sb0 + CB0_OFF + cur * CBUF_SZ;
        const float* hn = (const float*)(smem + CB0_OFF + cur * CBUF_SZ + 16384);

        // ---- HMMA filter (64 x 128 x 64) ----
        const int mrow0 = (wid & 3) * 16;
        const int ncol0 = (wid >> 2) * 64;
        const int q  = lane >> 3;
        const int rl = lane & 7;
        const int arow = (q & 1) * 8 + rl;
        const int akh  = q >> 1;
        const int brow = (q >> 1) * 8 + rl;
        const int bkh  = q & 1;

        float acc[8][4];
#pragma unroll
        for (int nt = 0; nt < 8; ++nt)
#pragma unroll
            for (int e = 0; e < 4; ++e) acc[nt][e] = 0.f;

#pragma unroll
        for (int kc = 0; kc < 4; ++kc) {
            unsigned int af[4];
            {
                int row = mrow0 + arow;
                unsigned int addr = sb0 + XB_OFF + row * 128
                                  + (((kc * 2 + akh) ^ (row & 7)) * 16);
                asm volatile("ldmatrix.sync.aligned.m8n8.x4.shared.b16 "
                             "{%0,%1,%2,%3}, [%4];"
                             : "=r"(af[0]), "=r"(af[1]), "=r"(af[2]), "=r"(af[3])
                             : "r"(addr));
            }
            unsigned int bf[4][4];
#pragma unroll
            for (int nt2 = 0; nt2 < 4; ++nt2) {
                int row = ncol0 + nt2 * 16 + brow;
                unsigned int addr = cbbase + row * 128
                                  + (((kc * 2 + bkh) ^ (row & 7)) * 16);
                asm volatile("ldmatrix.sync.aligned.m8n8.x4.shared.b16 "
                             "{%0,%1,%2,%3}, [%4];"
                             : "=r"(bf[nt2][0]), "=r"(bf[nt2][1]),
                               "=r"(bf[nt2][2]), "=r"(bf[nt2][3])
                             : "r"(addr));
            }
#pragma unroll
            for (int nt = 0; nt < 8; ++nt) {
                int nt2 = nt >> 1, hi = nt & 1;
                asm volatile(
                    "mma.sync.aligned.m16n8k16.row.col.f32.bf16.bf16.f32 "
                    "{%0,%1,%2,%3}, {%4,%5,%6,%7}, {%8,%9}, {%0,%1,%2,%3};"
                    : "+f"(acc[nt][0]), "+f"(acc[nt][1]),
                      "+f"(acc[nt][2]), "+f"(acc[nt][3])
                    : "r"(af[0]), "r"(af[1]), "r"(af[2]), "r"(af[3]),
                      "r"(bf[nt2][hi * 2]), "r"(bf[nt2][hi * 2 + 1]));
            }
        }

        // ---- per-row approx min -> smem (fkey atomicMin) ----
        const int r0 = mrow0 + (lane >> 2);
        const int r1 = r0 + 8;
        {
            float bv0 = 3.4e38f, bv1 = 3.4e38f;
#pragma unroll
            for (int nt = 0; nt < 8; ++nt) {
                int colb = ncol0 + nt * 8 + (lane & 3) * 2;
                float h0 = hn[colb], h1 = hn[colb + 1];
                bv0 = fminf(bv0, fminf(h0 - acc[nt][0], h1 - acc[nt][1]));
                bv1 = fminf(bv1, fminf(h0 - acc[nt][2], h1 - acc[nt][3]));
            }
            bv0 = fminf(bv0, __shfl_xor_sync(0xffffffffu, bv0, 1));
            bv0 = fminf(bv0, __shfl_xor_sync(0xffffffffu, bv0, 2));
            bv1 = fminf(bv1, __shfl_xor_sync(0xffffffffu, bv1, 1));
            bv1 = fminf(bv1, __shfl_xor_sync(0xffffffffu, bv1, 2));
            if ((lane & 3) == 0) {
                atomicMin(&srm[r0], fkey(bv0));
                atomicMin(&srm[r1], fkey(bv1));
            }
        }
        __syncthreads();

        // ---- branchless hitmask scan -> compact queue ----
        {
            const float T0 = fkey_dec(srm[r0]) + sS[r0] * 0.0158f + 0.002f;
            const float T1 = fkey_dec(srm[r1]) + sS[r1] * 0.0158f + 0.002f;
            unsigned int mask = 0;
#pragma unroll
            for (int nt = 0; nt < 8; ++nt) {
                int colb = ncol0 + nt * 8 + (lane & 3) * 2;
                float h0 = hn[colb], h1 = hn[colb + 1];
                mask |= (unsigned int)((h0 - acc[nt][0]) <= T0) << (nt * 4 + 0);
                mask |= (unsigned int)((h1 - acc[nt][1]) <= T0) << (nt * 4 + 1);
                mask |= (unsigned int)((h0 - acc[nt][2]) <= T1) << (nt * 4 + 2);
                mask |= (unsigned int)((h1 - acc[nt][3]) <= T1) << (nt * 4 + 3);
            }
            int cnt = __popc(mask);
            int incl = cnt;
#pragma unroll
            for (int off = 1; off < 32; off <<= 1) {
                int tmp = __shfl_up_sync(0xffffffffu, incl, off);
                if (lane >= off) incl += tmp;
            }
            int total = __shfl_sync(0xffffffffu, incl, 31);
            int base = 0;
            if (lane == 31 && total > 0) base = atomicAdd(qc, total);
            base = __shfl_sync(0xffffffffu, base, 31);
            int pos = base + incl - cnt;
            while (mask) {
                int bgd = __ffs(mask) - 1;
                mask &= mask - 1;
                int nt = bgd >> 2, j = bgd & 3;
                int row = (j < 2) ? r0 : r1;
                int col = ncol0 + nt * 8 + (lane & 3) * 2 + (j & 1);
                if (pos < QCAP) qu[pos] = (row << 8) | col;
                else atomicOr(&ovf[row >> 5], 1u << (row & 31));
                ++pos;
            }
        }
        __syncthreads();

        // ---- uniform exact fp32 verify: x from smem, c rows from L2 ----
        const int p  = t >> 3;
        const int s  = t & 7;
        const int n0 = p * TMV;
        const size_t cbgbase = (size_t)s * NTC * C_;
        int qn = *qc;
        if (qn > QCAP) qn = QCAP;
        for (int i = tid; i < qn; i += 256) {
            int e   = qu[i];
            int row = e >> 8;
            int col = e & 255;
            const float4* cr = (const float4*)&cb[cbgbase + (size_t)col * C_];
            float sv = hn[col];
#pragma unroll
            for (int c4 = 0; c4 < 16; ++c4) {
                float4 cv = cr[c4];
                sv = fmaf(-xf[(c4 * 4 + 0) * 64 + row], cv.x, sv);
                sv = fmaf(-xf[(c4 * 4 + 1) * 64 + row], cv.y, sv);
                sv = fmaf(-xf[(c4 * 4 + 2) * 64 + row], cv.z, sv);
                sv = fmaf(-xf[(c4 * 4 + 3) * 64 + row], cv.w, sv);
            }
            unsigned long long key =
                ((unsigned long long)fkey(sv) << 32)
                | (unsigned int)(s * NTC + col);
            atomicMin(&g_best[n0 + row], key);
        }

        // ---- overflow rows (queue full): exact rescan, ~never taken ----
        if (ovf[0] | ovf[1]) {
            for (int r = 0; r < TMV; ++r) {
                if (!(ovf[r >> 5] & (1u << (r & 31)))) continue;
                if (tid < NTC) {
                    int col = tid;
                    const float4* cr = (const float4*)&cb[cbgbase + (size_t)col * C_];
                    float sv = hn[col];
#pragma unroll
                    for (int c4 = 0; c4 < 16; ++c4) {
                        float4 cv = cr[c4];
                        sv = fmaf(-xf[(c4 * 4 + 0) * 64 + r], cv.x, sv);
                        sv = fmaf(-xf[(c4 * 4 + 1) * 64 + r], cv.y, sv);
                        sv = fmaf(-xf[(c4 * 4 + 2) * 64 + r], cv.z, sv);
                        sv = fmaf(-xf[(c4 * 4 + 3) * 64 + r], cv.w, sv);
                    }
                    unsigned long long key =
                        ((unsigned long long)fkey(sv) << 32)
                        | (unsigned int)(s * NTC + col);
                    atomicMin(&g_best[n0 + r], key);
                }
            }
        }
        __syncthreads();               // task fully consumed

        // ---- tile boundary: stage next tile's x + c ----
        if (tn < end && !same) {
            stage_x(sb0, z, tn >> 3, tid);
            stage_c(sb0 + CB0_OFF + (cur ^ 1) * CBUF_SZ, tn, tid);
            CP_COMMIT();
            needA = true;
        }

        t = tn;
        cur ^= 1;
    }

    grid_barrier(tid);                 // all g_best finalized

    // ==== Phase 2: finalize (32-point groups strided over blocks) ====
    float* scodes = xf;                // reuse smem (8320 B < 16384)
    int*   sidx   = (int*)srm;         // 32 ints < 256 B
    for (int fb = bid; fb < 1024; fb += NBLK) {
        const int n0  = fb * 32;
        const int b   = n0 >> 10;
        const int hw0 = n0 & 1023;

        if (tid < 32) {
            unsigned long long key = g_best[n0 + tid];
            int idx = (int)(unsigned int)(key & 0xFFFFFFFFull);
            sidx[tid] = idx;
            out[(size_t)B_ * C_ * HW_ + n0 + tid] = (float)idx;
        }
        __syncthreads();

#pragma unroll
        for (int i = 0; i < 2; ++i) {
            int idx = tid + i * 256;       // 0..511 float4s
            int m   = idx >> 4;
            int c4  = (idx & 15) * 4;
            float4 v = *(const float4*)&cb[sidx[m] * C_ + c4];
            scodes[m * 65 + c4 + 0] = v.x;
            scodes[m * 65 + c4 + 1] = v.y;
            scodes[m * 65 + c4 + 2] = v.z;
            scodes[m * 65 + c4 + 3] = v.w;
        }
        __syncthreads();

        {
            int m4    = (tid & 7) * 4;     // 0..28
            int cbase = tid >> 3;          // 0..31
            float* ob = out + (size_t)b * C_ * HW_ + hw0;
#pragma unroll
            for (int j = 0; j < 2; ++j) {
                int c = cbase + j * 32;
                float4 w;
                w.x = scodes[(m4 + 0) * 65 + c];
                w.y = scodes[(m4 + 1) * 65 + c];
                w.z = scodes[(m4 + 2) * 65 + c];
                w.w = scodes[(m4 + 3) * 65 + c];
                *(float4*)&ob[c * HW_ + m4] = w;
            }
        }
        __syncthreads();                   // scodes reuse next iteration
    }
}

// ---------------------------------------------------------------------------
extern "C" void kernel_launch(void* const* d_in, const int* in_sizes, int n_in,
                              void* d_out, int out_size) {
    const float* z  = (const float*)d_in[0];
    const float* cb = (const float*)d_in[1];
    float* out = (float*)d_out;
    (void)in_sizes; (void)n_in; (void)out_size;

    cudaFuncSetAttribute(vq_kernel,
                         cudaFuncAttributeMaxDynamicSharedMemorySize, SMEM_SZ);

    vq_kernel<<<NBLK, 256, SMEM_SZ>>>(z, cb, out);
}